// round 1
// baseline (speedup 1.0000x reference)
#include <cuda_runtime.h>
#include <cuda_bf16.h>

// Problem: single-head causal attention
// B=32, T=1024, C=384, H=64. Inputs: x[B,T,C], Wk[C,H], Wq[C,H], Wv[C,H] (fp32)
// Output: [B,T,H] fp32.

#define B_ 32
#define T_ 1024
#define C_ 384
#define H_ 64

// Scratch for projections (device globals: allocation-free).
__device__ float g_K[B_ * T_ * H_];
__device__ float g_Q[B_ * T_ * H_];
__device__ float g_V[B_ * T_ * H_];

// ---------------------------------------------------------------------------
// Projection kernel: out[b*T+t][h] = sum_c x[b*T+t][c] * W[c][h]
// Grid: (rows/128, 3). Block: 256 threads.
// Per-thread micro-tile: 8 rows x 4 cols (32 fp32 accumulators).
// x tile cached in smem (16 KB), W read via LDG.128 (stays L1-resident: 96 KB).
// ---------------------------------------------------------------------------
#define PB_ROWS 128
#define PB_CC   32

__global__ __launch_bounds__(256) void proj_kernel(
    const float* __restrict__ x,
    const float* __restrict__ Wk,
    const float* __restrict__ Wq,
    const float* __restrict__ Wv)
{
    __shared__ float xsm[PB_ROWS * PB_CC];

    const int w = blockIdx.y;
    const float* __restrict__ W = (w == 0) ? Wk : ((w == 1) ? Wq : Wv);
    float* __restrict__ out = (w == 0) ? g_K : ((w == 1) ? g_Q : g_V);

    const int row0 = blockIdx.x * PB_ROWS;
    const int t  = threadIdx.x;
    const int cg = t & 15;        // column group: h = cg*4 .. cg*4+3
    const int rg = t >> 4;        // row group: rows rg*8 .. rg*8+7

    float acc[8][4];
#pragma unroll
    for (int r = 0; r < 8; r++)
#pragma unroll
        for (int c = 0; c < 4; c++) acc[r][c] = 0.0f;

    for (int c0 = 0; c0 < C_; c0 += PB_CC) {
        __syncthreads();
        // Load x tile [128 rows x 32 cols], coalesced 128B per row-span.
#pragma unroll
        for (int i = t; i < PB_ROWS * PB_CC; i += 256) {
            int r = i >> 5, c = i & 31;
            xsm[i] = x[(size_t)(row0 + r) * C_ + c0 + c];
        }
        __syncthreads();

#pragma unroll 4
        for (int cc = 0; cc < PB_CC; cc++) {
            float4 wv = *reinterpret_cast<const float4*>(W + (c0 + cc) * H_ + cg * 4);
#pragma unroll
            for (int r = 0; r < 8; r++) {
                float xv = xsm[(rg * 8 + r) * PB_CC + cc];
                acc[r][0] += xv * wv.x;
                acc[r][1] += xv * wv.y;
                acc[r][2] += xv * wv.z;
                acc[r][3] += xv * wv.w;
            }
        }
    }

#pragma unroll
    for (int r = 0; r < 8; r++) {
        float4 o = make_float4(acc[r][0], acc[r][1], acc[r][2], acc[r][3]);
        *reinterpret_cast<float4*>(out + (size_t)(row0 + rg * 8 + r) * H_ + cg * 4) = o;
    }
}

// ---------------------------------------------------------------------------
// Flash-attention kernel (causal, online softmax).
// Grid: (T/64, B). Block: 128 threads.
// Each query row handled by a lane pair: lane (m,half) owns dims half*32..+31.
// Scores computed jointly via shfl_xor(1), staged in a swizzled 64x64 smem
// buffer ((s+m)&63 avoids bank conflicts at stride 64). 3 x 16 KB = 48 KB smem.
// ---------------------------------------------------------------------------
#define BM 64
#define BN 64

__global__ __launch_bounds__(128) void attn_kernel(float* __restrict__ out)
{
    __shared__ float Ks[BN * H_];
    __shared__ float Vs[BN * H_];
    __shared__ float Sc[BM * BN];

    const int b  = blockIdx.y;
    const int q0 = blockIdx.x * BM;
    const int t  = threadIdx.x;
    const int m    = t >> 1;      // query within tile: 0..63
    const int half = t & 1;       // dim half
    const int off  = half * 32;
    const int qg   = q0 + m;      // global query index

    // Load this thread's 32 q dims into registers.
    const float* qrow = g_Q + ((size_t)(b << 10) + qg) * H_ + off;
    float4 q[8];
#pragma unroll
    for (int jj = 0; jj < 8; jj++)
        q[jj] = *reinterpret_cast<const float4*>(qrow + jj * 4);

    float acc[32];
#pragma unroll
    for (int j = 0; j < 32; j++) acc[j] = 0.0f;
    float row_max = -1e30f;
    float row_sum = 0.0f;

    for (int n0 = 0; n0 <= q0; n0 += BN) {
        __syncthreads();  // protect prior-iteration reads of Vs/Sc

        // Cooperative K/V tile load (float4, fully coalesced).
        {
            const float4* Kg = reinterpret_cast<const float4*>(g_K + ((size_t)(b << 10) + n0) * H_);
            const float4* Vg = reinterpret_cast<const float4*>(g_V + ((size_t)(b << 10) + n0) * H_);
            float4* Ks4 = reinterpret_cast<float4*>(Ks);
            float4* Vs4 = reinterpret_cast<float4*>(Vs);
#pragma unroll
            for (int i = t; i < BN * H_ / 4; i += 128) {
                Ks4[i] = Kg[i];
                Vs4[i] = Vg[i];
            }
        }
        __syncthreads();

        const bool diag = (n0 == q0);
        float tmax = -1e30f;

        // Phase 1: scores for all 64 keys (each lane pair jointly).
        for (int s = 0; s < BN; s++) {
            const float4* kr = reinterpret_cast<const float4*>(Ks + s * H_ + off);
            float d = 0.0f;
#pragma unroll
            for (int jj = 0; jj < 8; jj++) {
                float4 kv = kr[jj];
                d += q[jj].x * kv.x + q[jj].y * kv.y + q[jj].z * kv.z + q[jj].w * kv.w;
            }
            d += __shfl_xor_sync(0xffffffffu, d, 1);
            d *= 0.125f;  // H^-0.5
            if (diag && (n0 + s > qg)) d = -1e30f;
            tmax = fmaxf(tmax, d);
            if (half == 0) Sc[(m << 6) + ((s + m) & 63)] = d;
        }
        __syncthreads();

        // Phase 2: online softmax + PV accumulate (rescale once per tile).
        float nm    = fmaxf(row_max, tmax);
        float alpha = __expf(row_max - nm);
        row_sum *= alpha;
#pragma unroll
        for (int j = 0; j < 32; j++) acc[j] *= alpha;

        for (int s = 0; s < BN; s++) {
            float p = __expf(Sc[(m << 6) + ((s + m) & 63)] - nm);
            row_sum += p;
            const float4* vr = reinterpret_cast<const float4*>(Vs + s * H_ + off);
#pragma unroll
            for (int jj = 0; jj < 8; jj++) {
                float4 vv = vr[jj];
                acc[jj * 4 + 0] += p * vv.x;
                acc[jj * 4 + 1] += p * vv.y;
                acc[jj * 4 + 2] += p * vv.z;
                acc[jj * 4 + 3] += p * vv.w;
            }
        }
        row_max = nm;
    }

    const float inv = 1.0f / row_sum;
    float* orow = out + ((size_t)(b << 10) + qg) * H_ + off;
#pragma unroll
    for (int jj = 0; jj < 8; jj++) {
        float4 o = make_float4(acc[jj * 4 + 0] * inv, acc[jj * 4 + 1] * inv,
                               acc[jj * 4 + 2] * inv, acc[jj * 4 + 3] * inv);
        *reinterpret_cast<float4*>(orow + jj * 4) = o;
    }
}

// ---------------------------------------------------------------------------
extern "C" void kernel_launch(void* const* d_in, const int* in_sizes, int n_in,
                              void* d_out, int out_size)
{
    const float* x  = (const float*)d_in[0];
    const float* Wk = (const float*)d_in[1];
    const float* Wq = (const float*)d_in[2];
    const float* Wv = (const float*)d_in[3];
    float* out = (float*)d_out;

    dim3 pg((B_ * T_) / PB_ROWS, 3);
    proj_kernel<<<pg, 256>>>(x, Wk, Wq, Wv);

    dim3 ag(T_ / BM, B_);
    attn_kernel<<<ag, 128>>>(out);
}

// round 5
// speedup vs baseline: 2.5494x; 2.5494x over previous
#include <cuda_runtime.h>
#include <cstdint>

// Single-head causal attention: B=32, T=1024, C=384, H=64 (fp32 in/out).
#define B_ 32
#define T_ 1024
#define C_ 384
#define H_ 64

__device__ float g_K[B_ * T_ * H_];
__device__ float g_Q[B_ * T_ * H_];
__device__ float g_V[B_ * T_ * H_];

// ---------------------------------------------------------------------------
// Legacy-PTX tensor helpers (valid on base sm_103 target).
// ---------------------------------------------------------------------------
__device__ __forceinline__ float to_tf32(float x) {
    float r;
    asm("cvt.rna.tf32.f32 %0, %1;" : "=f"(r) : "f"(x));
    return r;
}

__device__ __forceinline__ void mma_tf32_16x8x8(
    float& d0, float& d1, float& d2, float& d3,
    uint32_t a0, uint32_t a1, uint32_t a2, uint32_t a3,
    uint32_t b0, uint32_t b1)
{
    asm volatile(
        "mma.sync.aligned.m16n8k8.row.col.f32.tf32.tf32.f32 "
        "{%0,%1,%2,%3}, {%4,%5,%6,%7}, {%8,%9}, {%0,%1,%2,%3};"
        : "+f"(d0), "+f"(d1), "+f"(d2), "+f"(d3)
        : "r"(a0), "r"(a1), "r"(a2), "r"(a3), "r"(b0), "r"(b1));
}

// ===========================================================================
// Projection GEMM (mma.sync tf32): out[32768,64] = x[32768,384] @ W[384,64]
// CTA: 128 rows, 256 threads = 8 warps; warp tile = 16 rows x 64 cols.
// K chunks of 32 via smem. Pad strides: sA 36 (A-frag LDS conflict-free),
// sB 72 (B-frag LDS conflict-free).
// ===========================================================================
#define PM 128
#define PKC 32
#define SA_STR 36
#define SB_STR 72

__global__ void __launch_bounds__(256, 2) proj_mma(
    const float* __restrict__ x,
    const float* __restrict__ Wk,
    const float* __restrict__ Wq,
    const float* __restrict__ Wv)
{
    __shared__ float sA[PM * SA_STR];      // 18 KB
    __shared__ float sB[PKC * SB_STR];     //  9 KB

    const int t = threadIdx.x;
    const int wid = t >> 5;
    const int lane = t & 31;
    const int g = lane >> 2;       // groupID 0..7
    const int tig = lane & 3;      // thread-in-group 0..3
    const int wr0 = wid * 16;      // warp's row base within CTA tile

    const int w = blockIdx.y;
    const float* __restrict__ W = (w == 0) ? Wk : ((w == 1) ? Wq : Wv);
    float* __restrict__ out = (w == 0) ? g_K : ((w == 1) ? g_Q : g_V);
    const int row0 = blockIdx.x * PM;

    float acc[8][4];
#pragma unroll
    for (int nt = 0; nt < 8; nt++)
#pragma unroll
        for (int i = 0; i < 4; i++) acc[nt][i] = 0.0f;

    for (int c0 = 0; c0 < C_; c0 += PKC) {
        __syncthreads();
        // Load A tile: x[row0..+127][c0..+31], tf32-rounded.
#pragma unroll
        for (int i = 0; i < 4; i++) {
            int f = t + i * 256;              // float4 idx 0..1023
            int row = f >> 3;
            int c4 = (f & 7) * 4;
            float4 v = *reinterpret_cast<const float4*>(
                x + (size_t)(row0 + row) * C_ + c0 + c4);
            float* d = &sA[row * SA_STR + c4];
            d[0] = to_tf32(v.x); d[1] = to_tf32(v.y);
            d[2] = to_tf32(v.z); d[3] = to_tf32(v.w);
        }
        // Load B tile: W[c0+k][n] -> sB[k][n], tf32-rounded.
#pragma unroll
        for (int i = 0; i < 2; i++) {
            int f = t + i * 256;              // float4 idx 0..511
            int k = f >> 4;
            int n4 = (f & 15) * 4;
            float4 v = *reinterpret_cast<const float4*>(W + (size_t)(c0 + k) * H_ + n4);
            float* d = &sB[k * SB_STR + n4];
            d[0] = to_tf32(v.x); d[1] = to_tf32(v.y);
            d[2] = to_tf32(v.z); d[3] = to_tf32(v.w);
        }
        __syncthreads();

#pragma unroll
        for (int ks = 0; ks < 4; ks++) {
            const int k8 = ks * 8;
            // A fragment (16x8)
            uint32_t a0 = __float_as_uint(sA[(wr0 + g) * SA_STR + k8 + tig]);
            uint32_t a1 = __float_as_uint(sA[(wr0 + g + 8) * SA_STR + k8 + tig]);
            uint32_t a2 = __float_as_uint(sA[(wr0 + g) * SA_STR + k8 + tig + 4]);
            uint32_t a3 = __float_as_uint(sA[(wr0 + g + 8) * SA_STR + k8 + tig + 4]);
#pragma unroll
            for (int nt = 0; nt < 8; nt++) {
                uint32_t b0 = __float_as_uint(sB[(k8 + tig) * SB_STR + nt * 8 + g]);
                uint32_t b1 = __float_as_uint(sB[(k8 + tig + 4) * SB_STR + nt * 8 + g]);
                mma_tf32_16x8x8(acc[nt][0], acc[nt][1], acc[nt][2], acc[nt][3],
                                a0, a1, a2, a3, b0, b1);
            }
        }
    }

    // Epilogue: c0/c1 -> (row g, cols 2tig,2tig+1), c2/c3 -> row g+8.
#pragma unroll
    for (int nt = 0; nt < 8; nt++) {
        float* o0 = out + (size_t)(row0 + wr0 + g) * H_ + nt * 8 + 2 * tig;
        o0[0] = acc[nt][0]; o0[1] = acc[nt][1];
        float* o1 = out + (size_t)(row0 + wr0 + g + 8) * H_ + nt * 8 + 2 * tig;
        o1[0] = acc[nt][2]; o1[1] = acc[nt][3];
    }
}

// ===========================================================================
// Register-tiled flash attention (fp32 CUDA cores).
// Block: 256 threads (16x16), tile 64q x 64k. Thread owns 4x4 of S/P and O.
// smem: Qt [h][q] 16KB, KV union (Kt [h][k] then V [k][h]) 16KB,
//       Ps swizzled [q][(s+4q)&63] 16KB. Total 48KB static.
// ===========================================================================
#define BM 64
#define BN 64

__global__ void __launch_bounds__(256, 3) attn2(float* __restrict__ out)
{
    __shared__ float Qt[64 * 64];
    __shared__ float KV[64 * 64];
    __shared__ float Ps[64 * 64];

    const int b = blockIdx.y;
    const int q0 = ((int)gridDim.x - 1 - (int)blockIdx.x) * BM;  // heavy blocks first
    const int t = threadIdx.x;
    const int tx = t & 15;
    const int ty = t >> 4;
    const float cs = 0.125f * 1.44269504f;   // scale * log2(e)

    // Load + transpose Q tile once.
    {
        const float* Qg = g_Q + ((size_t)(b << 10) + q0) * H_;
        int q = t & 63, hb = (t >> 6) * 16;
#pragma unroll
        for (int i = 0; i < 4; i++) {
            float4 v = *reinterpret_cast<const float4*>(Qg + q * H_ + hb + i * 4);
            Qt[(hb + i * 4 + 0) * 64 + q] = v.x;
            Qt[(hb + i * 4 + 1) * 64 + q] = v.y;
            Qt[(hb + i * 4 + 2) * 64 + q] = v.z;
            Qt[(hb + i * 4 + 3) * 64 + q] = v.w;
        }
    }

    float o[4][4];
    float rmax[4], rsum[4];
#pragma unroll
    for (int i = 0; i < 4; i++) {
        rmax[i] = -1e30f; rsum[i] = 0.0f;
#pragma unroll
        for (int j = 0; j < 4; j++) o[i][j] = 0.0f;
    }

    const int ntiles = q0 / BN + 1;
    for (int nt = 0; nt < ntiles; nt++) {
        const int n0 = nt * BN;
        __syncthreads();   // prior iteration done with KV/Ps

        // Load + transpose K tile into KV ( Kt[h][key] ).
        {
            const float* Kg = g_K + ((size_t)(b << 10) + n0) * H_;
            int k = t & 63, hb = (t >> 6) * 16;
#pragma unroll
            for (int i = 0; i < 4; i++) {
                float4 v = *reinterpret_cast<const float4*>(Kg + k * H_ + hb + i * 4);
                KV[(hb + i * 4 + 0) * 64 + k] = v.x;
                KV[(hb + i * 4 + 1) * 64 + k] = v.y;
                KV[(hb + i * 4 + 2) * 64 + k] = v.z;
                KV[(hb + i * 4 + 3) * 64 + k] = v.w;
            }
        }
        __syncthreads();

        // S-GEMM: s[i][j] = q(4ty+i) . k(4tx+j)
        float s[4][4];
#pragma unroll
        for (int i = 0; i < 4; i++)
#pragma unroll
            for (int j = 0; j < 4; j++) s[i][j] = 0.0f;

#pragma unroll 8
        for (int h = 0; h < 64; h++) {
            float4 qv = *reinterpret_cast<const float4*>(&Qt[h * 64 + 4 * ty]);
            float4 kv = *reinterpret_cast<const float4*>(&KV[h * 64 + 4 * tx]);
            const float qa[4] = {qv.x, qv.y, qv.z, qv.w};
            const float ka[4] = {kv.x, kv.y, kv.z, kv.w};
#pragma unroll
            for (int i = 0; i < 4; i++)
#pragma unroll
                for (int j = 0; j < 4; j++) s[i][j] += qa[i] * ka[j];
        }

        // Causal mask on diagonal tile.
        if (n0 == q0) {
#pragma unroll
            for (int i = 0; i < 4; i++)
#pragma unroll
                for (int j = 0; j < 4; j++)
                    if (4 * tx + j > 4 * ty + i) s[i][j] = -1e30f;
        }

        // Row max over the 16-lane tx group.
        float tmax[4];
#pragma unroll
        for (int i = 0; i < 4; i++)
            tmax[i] = fmaxf(fmaxf(s[i][0], s[i][1]), fmaxf(s[i][2], s[i][3]));
#pragma unroll
        for (int d = 1; d < 16; d <<= 1)
#pragma unroll
            for (int i = 0; i < 4; i++)
                tmax[i] = fmaxf(tmax[i], __shfl_xor_sync(0xffffffffu, tmax[i], d));

        // Online softmax update.
        float psum[4];
#pragma unroll
        for (int i = 0; i < 4; i++) {
            float nm = fmaxf(rmax[i], tmax[i]);
            float al = exp2f((rmax[i] - nm) * cs);
            rmax[i] = nm;
            rsum[i] *= al;
#pragma unroll
            for (int j = 0; j < 4; j++) o[i][j] *= al;
            float p0 = exp2f((s[i][0] - nm) * cs);
            float p1 = exp2f((s[i][1] - nm) * cs);
            float p2 = exp2f((s[i][2] - nm) * cs);
            float p3 = exp2f((s[i][3] - nm) * cs);
            s[i][0] = p0; s[i][1] = p1; s[i][2] = p2; s[i][3] = p3;
            psum[i] = (p0 + p1) + (p2 + p3);
        }
#pragma unroll
        for (int d = 1; d < 16; d <<= 1)
#pragma unroll
            for (int i = 0; i < 4; i++)
                psum[i] += __shfl_xor_sync(0xffffffffu, psum[i], d);
#pragma unroll
        for (int i = 0; i < 4; i++) rsum[i] += psum[i];

        // Write P to swizzled smem: P[r][c] at Ps[r][(c+4r)&63].
#pragma unroll
        for (int i = 0; i < 4; i++) {
            int r = 4 * ty + i;
            int col = (4 * tx + 4 * r) & 63;
            *reinterpret_cast<float4*>(&Ps[r * 64 + col]) =
                make_float4(s[i][0], s[i][1], s[i][2], s[i][3]);
        }
        __syncthreads();   // Ps complete; KV (Kt) no longer needed

        // Load V tile into KV ( V[key][h] ).
        {
            const float4* Vg4 = reinterpret_cast<const float4*>(
                g_V + ((size_t)(b << 10) + n0) * H_);
            float4* KV4 = reinterpret_cast<float4*>(KV);
#pragma unroll
            for (int i = 0; i < 4; i++) KV4[t + i * 256] = Vg4[t + i * 256];
        }
        __syncthreads();

        // PV: o[i][j] += P[r][s] * V[s][4tx+j]
#pragma unroll 2
        for (int s0 = 0; s0 < 64; s0 += 4) {
            float4 pl[4];
#pragma unroll
            for (int i = 0; i < 4; i++) {
                int r = 4 * ty + i;
                pl[i] = *reinterpret_cast<const float4*>(&Ps[r * 64 + ((s0 + 4 * r) & 63)]);
            }
            float4 vv[4];
#pragma unroll
            for (int ss = 0; ss < 4; ss++)
                vv[ss] = *reinterpret_cast<const float4*>(&KV[(s0 + ss) * 64 + 4 * tx]);
#pragma unroll
            for (int i = 0; i < 4; i++) {
                o[i][0] += pl[i].x * vv[0].x; o[i][1] += pl[i].x * vv[0].y;
                o[i][2] += pl[i].x * vv[0].z; o[i][3] += pl[i].x * vv[0].w;
                o[i][0] += pl[i].y * vv[1].x; o[i][1] += pl[i].y * vv[1].y;
                o[i][2] += pl[i].y * vv[1].z; o[i][3] += pl[i].y * vv[1].w;
                o[i][0] += pl[i].z * vv[2].x; o[i][1] += pl[i].z * vv[2].y;
                o[i][2] += pl[i].z * vv[2].z; o[i][3] += pl[i].z * vv[2].w;
                o[i][0] += pl[i].w * vv[3].x; o[i][1] += pl[i].w * vv[3].y;
                o[i][2] += pl[i].w * vv[3].z; o[i][3] += pl[i].w * vv[3].w;
            }
        }
    }

    // Write output.
#pragma unroll
    for (int i = 0; i < 4; i++) {
        int r = q0 + 4 * ty + i;
        float inv = 1.0f / rsum[i];
        float4 v = make_float4(o[i][0] * inv, o[i][1] * inv, o[i][2] * inv, o[i][3] * inv);
        *reinterpret_cast<float4*>(out + ((size_t)(b << 10) + r) * H_ + 4 * tx) = v;
    }
}

// ===========================================================================
extern "C" void kernel_launch(void* const* d_in, const int* in_sizes, int n_in,
                              void* d_out, int out_size)
{
    const float* x  = (const float*)d_in[0];
    const float* Wk = (const float*)d_in[1];
    const float* Wq = (const float*)d_in[2];
    const float* Wv = (const float*)d_in[3];
    float* out = (float*)d_out;

    dim3 pg((B_ * T_) / PM, 3);
    proj_mma<<<pg, 256>>>(x, Wk, Wq, Wv);

    dim3 ag(T_ / BM, B_);
    attn2<<<ag, 256>>>(out);
}

// round 7
// speedup vs baseline: 4.9406x; 1.9380x over previous
#include <cuda_runtime.h>
#include <cstdint>

// Single-head causal attention: B=32, T=1024, C=384, H=64 (fp32 in/out).
#define B_ 32
#define T_ 1024
#define C_ 384
#define H_ 64

__device__ float g_K[B_ * T_ * H_];
__device__ float g_Q[B_ * T_ * H_];
__device__ float g_V[B_ * T_ * H_];

// ---------------------------------------------------------------------------
// Legacy-PTX tensor helpers (valid on base sm_103 target).
// ---------------------------------------------------------------------------
__device__ __forceinline__ float to_tf32(float x) {
    float r;
    asm("cvt.rna.tf32.f32 %0, %1;" : "=f"(r) : "f"(x));
    return r;
}

__device__ __forceinline__ void mma_tf32_16x8x8(
    float& d0, float& d1, float& d2, float& d3,
    uint32_t a0, uint32_t a1, uint32_t a2, uint32_t a3,
    uint32_t b0, uint32_t b1)
{
    asm volatile(
        "mma.sync.aligned.m16n8k8.row.col.f32.tf32.tf32.f32 "
        "{%0,%1,%2,%3}, {%4,%5,%6,%7}, {%8,%9}, {%0,%1,%2,%3};"
        : "+f"(d0), "+f"(d1), "+f"(d2), "+f"(d3)
        : "r"(a0), "r"(a1), "r"(a2), "r"(a3), "r"(b0), "r"(b1));
}

// ===========================================================================
// Projection GEMM (mma.sync tf32): out[32768,64] = x[32768,384] @ W[384,64]
// (validated round 5: rel_err contribution ~4.6e-4, ~47us)
// ===========================================================================
#define PM 128
#define PKC 32
#define SA_STR 36
#define SB_STR 72

__global__ void __launch_bounds__(256, 2) proj_mma(
    const float* __restrict__ x,
    const float* __restrict__ Wk,
    const float* __restrict__ Wq,
    const float* __restrict__ Wv)
{
    __shared__ float sA[PM * SA_STR];      // 18 KB
    __shared__ float sB[PKC * SB_STR];     //  9 KB

    const int t = threadIdx.x;
    const int wid = t >> 5;
    const int lane = t & 31;
    const int g = lane >> 2;
    const int tig = lane & 3;
    const int wr0 = wid * 16;

    const int w = blockIdx.y;
    const float* __restrict__ W = (w == 0) ? Wk : ((w == 1) ? Wq : Wv);
    float* __restrict__ out = (w == 0) ? g_K : ((w == 1) ? g_Q : g_V);
    const int row0 = blockIdx.x * PM;

    float acc[8][4];
#pragma unroll
    for (int nt = 0; nt < 8; nt++)
#pragma unroll
        for (int i = 0; i < 4; i++) acc[nt][i] = 0.0f;

    for (int c0 = 0; c0 < C_; c0 += PKC) {
        __syncthreads();
#pragma unroll
        for (int i = 0; i < 4; i++) {
            int f = t + i * 256;
            int row = f >> 3;
            int c4 = (f & 7) * 4;
            float4 v = *reinterpret_cast<const float4*>(
                x + (size_t)(row0 + row) * C_ + c0 + c4);
            float* d = &sA[row * SA_STR + c4];
            d[0] = to_tf32(v.x); d[1] = to_tf32(v.y);
            d[2] = to_tf32(v.z); d[3] = to_tf32(v.w);
        }
#pragma unroll
        for (int i = 0; i < 2; i++) {
            int f = t + i * 256;
            int k = f >> 4;
            int n4 = (f & 15) * 4;
            float4 v = *reinterpret_cast<const float4*>(W + (size_t)(c0 + k) * H_ + n4);
            float* d = &sB[k * SB_STR + n4];
            d[0] = to_tf32(v.x); d[1] = to_tf32(v.y);
            d[2] = to_tf32(v.z); d[3] = to_tf32(v.w);
        }
        __syncthreads();

#pragma unroll
        for (int ks = 0; ks < 4; ks++) {
            const int k8 = ks * 8;
            uint32_t a0 = __float_as_uint(sA[(wr0 + g) * SA_STR + k8 + tig]);
            uint32_t a1 = __float_as_uint(sA[(wr0 + g + 8) * SA_STR + k8 + tig]);
            uint32_t a2 = __float_as_uint(sA[(wr0 + g) * SA_STR + k8 + tig + 4]);
            uint32_t a3 = __float_as_uint(sA[(wr0 + g + 8) * SA_STR + k8 + tig + 4]);
#pragma unroll
            for (int nt = 0; nt < 8; nt++) {
                uint32_t b0 = __float_as_uint(sB[(k8 + tig) * SB_STR + nt * 8 + g]);
                uint32_t b1 = __float_as_uint(sB[(k8 + tig + 4) * SB_STR + nt * 8 + g]);
                mma_tf32_16x8x8(acc[nt][0], acc[nt][1], acc[nt][2], acc[nt][3],
                                a0, a1, a2, a3, b0, b1);
            }
        }
    }

#pragma unroll
    for (int nt = 0; nt < 8; nt++) {
        float* o0 = out + (size_t)(row0 + wr0 + g) * H_ + nt * 8 + 2 * tig;
        o0[0] = acc[nt][0]; o0[1] = acc[nt][1];
        float* o1 = out + (size_t)(row0 + wr0 + g + 8) * H_ + nt * 8 + 2 * tig;
        o1[0] = acc[nt][2]; o1[1] = acc[nt][3];
    }
}

// ===========================================================================
// Tensor-core flash attention (mma.sync tf32).
// Block 128 thr = 4 warps; q-tile 64 (16 rows/warp), key-tile 64.
// smem: Ks stride 68 (B-frag banks 4g+tig: conflict-free),
//       Vs stride 72 (B-frag banks 8tig+g: conflict-free). 35 KB.
// P accum->A-operand conversion via intra-quad shfl + parity select.
// ===========================================================================
#define KS_STR 68
#define VS_STR 72

__global__ void __launch_bounds__(128) attn_mma(float* __restrict__ out)
{
    __shared__ float Ks[64 * KS_STR];
    __shared__ float Vs[64 * VS_STR];

    const int b = blockIdx.y;
    const int q0 = (15 - (int)blockIdx.x) * 64;   // heavy blocks first
    const int t = threadIdx.x;
    const int wid = t >> 5;
    const int lane = t & 31;
    const int g = lane >> 2;
    const int tig = lane & 3;
    const int m0 = wid * 16 + g;                  // warp row (and m0+8) in q-tile
    const float cs = 0.125f * 1.44269504f;        // H^-0.5 * log2(e), folded into Q

    // --- Stage Q'' (scaled, tf32-rounded) through Ks, extract A-fragments.
    {
        const float* Qg = g_Q + ((size_t)(b << 10) + q0) * H_;
#pragma unroll
        for (int i = 0; i < 8; i++) {
            int f4 = t + i * 128;
            int row = f4 >> 4, c4 = (f4 & 15) << 2;
            float4 v = *reinterpret_cast<const float4*>(Qg + row * H_ + c4);
            *reinterpret_cast<float4*>(&Ks[row * KS_STR + c4]) =
                make_float4(to_tf32(v.x * cs), to_tf32(v.y * cs),
                            to_tf32(v.z * cs), to_tf32(v.w * cs));
        }
    }
    __syncthreads();
    uint32_t q[8][4];
#pragma unroll
    for (int kc = 0; kc < 8; kc++) {
        q[kc][0] = __float_as_uint(Ks[m0 * KS_STR + kc * 8 + tig]);
        q[kc][1] = __float_as_uint(Ks[(m0 + 8) * KS_STR + kc * 8 + tig]);
        q[kc][2] = __float_as_uint(Ks[m0 * KS_STR + kc * 8 + tig + 4]);
        q[kc][3] = __float_as_uint(Ks[(m0 + 8) * KS_STR + kc * 8 + tig + 4]);
    }

    float o[8][4];
#pragma unroll
    for (int nt = 0; nt < 8; nt++)
#pragma unroll
        for (int i = 0; i < 4; i++) o[nt][i] = 0.0f;
    float rmaxA = -1e30f, rmaxB = -1e30f, rsumA = 0.0f, rsumB = 0.0f;

    const int ntiles = q0 / 64 + 1;
    for (int ti = 0; ti < ntiles; ti++) {
        const int n0 = ti * 64;
        __syncthreads();   // everyone done with Ks/Vs (and Q staging on iter 0)

        // --- Cooperative K/V tile load, tf32-rounded.
        {
            const float* Kg = g_K + ((size_t)(b << 10) + n0) * H_;
            const float* Vg = g_V + ((size_t)(b << 10) + n0) * H_;
#pragma unroll
            for (int i = 0; i < 8; i++) {
                int f4 = t + i * 128;
                int row = f4 >> 4, c4 = (f4 & 15) << 2;
                float4 v = *reinterpret_cast<const float4*>(Kg + row * H_ + c4);
                *reinterpret_cast<float4*>(&Ks[row * KS_STR + c4]) =
                    make_float4(to_tf32(v.x), to_tf32(v.y), to_tf32(v.z), to_tf32(v.w));
                float4 u = *reinterpret_cast<const float4*>(Vg + row * H_ + c4);
                *reinterpret_cast<float4*>(&Vs[row * VS_STR + c4]) =
                    make_float4(to_tf32(u.x), to_tf32(u.y), to_tf32(u.z), to_tf32(u.w));
            }
        }
        __syncthreads();

        // --- S = Q''.K^T  (64 MMAs/warp). B-frag: b0=K[nt8+g][kc8+tig].
        float s[8][4];
#pragma unroll
        for (int nt = 0; nt < 8; nt++)
#pragma unroll
            for (int i = 0; i < 4; i++) s[nt][i] = 0.0f;

#pragma unroll
        for (int kc = 0; kc < 8; kc++) {
#pragma unroll
            for (int nt = 0; nt < 8; nt++) {
                uint32_t b0 = __float_as_uint(Ks[(nt * 8 + g) * KS_STR + kc * 8 + tig]);
                uint32_t b1 = __float_as_uint(Ks[(nt * 8 + g) * KS_STR + kc * 8 + tig + 4]);
                mma_tf32_16x8x8(s[nt][0], s[nt][1], s[nt][2], s[nt][3],
                                q[kc][0], q[kc][1], q[kc][2], q[kc][3], b0, b1);
            }
        }

        // --- Causal mask on diagonal tile. s cols: nt8+2tig(+1); rows m0, m0+8.
        if (n0 == q0) {
#pragma unroll
            for (int nt = 0; nt < 8; nt++) {
                int c0 = nt * 8 + 2 * tig;
                if (c0 > m0)     s[nt][0] = -1e30f;
                if (c0 + 1 > m0) s[nt][1] = -1e30f;
                if (c0 > m0 + 8)     s[nt][2] = -1e30f;
                if (c0 + 1 > m0 + 8) s[nt][3] = -1e30f;
            }
        }

        // --- Online softmax (rows spread over the 4 tig lanes: shfl_xor 1,2).
        float tA = -1e30f, tB = -1e30f;
#pragma unroll
        for (int nt = 0; nt < 8; nt++) {
            tA = fmaxf(tA, fmaxf(s[nt][0], s[nt][1]));
            tB = fmaxf(tB, fmaxf(s[nt][2], s[nt][3]));
        }
        tA = fmaxf(tA, __shfl_xor_sync(0xffffffffu, tA, 1));
        tA = fmaxf(tA, __shfl_xor_sync(0xffffffffu, tA, 2));
        tB = fmaxf(tB, __shfl_xor_sync(0xffffffffu, tB, 1));
        tB = fmaxf(tB, __shfl_xor_sync(0xffffffffu, tB, 2));

        float nmA = fmaxf(rmaxA, tA), nmB = fmaxf(rmaxB, tB);
        float alA = exp2f(rmaxA - nmA), alB = exp2f(rmaxB - nmB);
        rmaxA = nmA; rmaxB = nmB;
        rsumA *= alA; rsumB *= alB;
#pragma unroll
        for (int nt = 0; nt < 8; nt++) {
            o[nt][0] *= alA; o[nt][1] *= alA;
            o[nt][2] *= alB; o[nt][3] *= alB;
        }

        float psA = 0.0f, psB = 0.0f;
#pragma unroll
        for (int nt = 0; nt < 8; nt++) {
            float p0 = to_tf32(exp2f(s[nt][0] - nmA));
            float p1 = to_tf32(exp2f(s[nt][1] - nmA));
            float p2 = to_tf32(exp2f(s[nt][2] - nmB));
            float p3 = to_tf32(exp2f(s[nt][3] - nmB));
            s[nt][0] = p0; s[nt][1] = p1; s[nt][2] = p2; s[nt][3] = p3;
            psA += p0 + p1; psB += p2 + p3;
        }
        psA += __shfl_xor_sync(0xffffffffu, psA, 1);
        psA += __shfl_xor_sync(0xffffffffu, psA, 2);
        psB += __shfl_xor_sync(0xffffffffu, psB, 1);
        psB += __shfl_xor_sync(0xffffffffu, psB, 2);
        rsumA += psA; rsumB += psB;

        // --- O += P.V  (64 MMAs/warp). A-frag built from P accum frags via
        // intra-quad shfl: col tig held by lane tig>>1 (comp 0/1 by parity).
        const int srcA = (lane & ~3) | (tig >> 1);
        const int srcB = srcA + 2;
        const bool odd = (tig & 1) != 0;
#pragma unroll
        for (int kc = 0; kc < 8; kc++) {
            float e0 = __shfl_sync(0xffffffffu, s[kc][0], srcA);
            float e1 = __shfl_sync(0xffffffffu, s[kc][1], srcA);
            float e2 = __shfl_sync(0xffffffffu, s[kc][2], srcA);
            float e3 = __shfl_sync(0xffffffffu, s[kc][3], srcA);
            float f0 = __shfl_sync(0xffffffffu, s[kc][0], srcB);
            float f1 = __shfl_sync(0xffffffffu, s[kc][1], srcB);
            float f2 = __shfl_sync(0xffffffffu, s[kc][2], srcB);
            float f3 = __shfl_sync(0xffffffffu, s[kc][3], srcB);
            uint32_t a0 = __float_as_uint(odd ? e1 : e0);
            uint32_t a1 = __float_as_uint(odd ? e3 : e2);
            uint32_t a2 = __float_as_uint(odd ? f1 : f0);
            uint32_t a3 = __float_as_uint(odd ? f3 : f2);
#pragma unroll
            for (int nt = 0; nt < 8; nt++) {
                uint32_t b0 = __float_as_uint(Vs[(kc * 8 + tig) * VS_STR + nt * 8 + g]);
                uint32_t b1 = __float_as_uint(Vs[(kc * 8 + tig + 4) * VS_STR + nt * 8 + g]);
                mma_tf32_16x8x8(o[nt][0], o[nt][1], o[nt][2], o[nt][3],
                                a0, a1, a2, a3, b0, b1);
            }
        }
    }

    // --- Normalize + write. Rows m0, m0+8; cols nt8+2tig(+1).
    const float invA = 1.0f / rsumA, invB = 1.0f / rsumB;
    float* OrA = out + ((size_t)(b << 10) + q0 + m0) * H_;
    float* OrB = OrA + 8 * H_;
#pragma unroll
    for (int nt = 0; nt < 8; nt++) {
        *reinterpret_cast<float2*>(OrA + nt * 8 + 2 * tig) =
            make_float2(o[nt][0] * invA, o[nt][1] * invA);
        *reinterpret_cast<float2*>(OrB + nt * 8 + 2 * tig) =
            make_float2(o[nt][2] * invB, o[nt][3] * invB);
    }
}

// ===========================================================================
extern "C" void kernel_launch(void* const* d_in, const int* in_sizes, int n_in,
                              void* d_out, int out_size)
{
    const float* x  = (const float*)d_in[0];
    const float* Wk = (const float*)d_in[1];
    const float* Wq = (const float*)d_in[2];
    const float* Wv = (const float*)d_in[3];
    float* out = (float*)d_out;

    dim3 pg((B_ * T_) / PM, 3);
    proj_mma<<<pg, 256>>>(x, Wk, Wq, Wv);

    dim3 ag(T_ / 64, B_);
    attn_mma<<<ag, 128>>>(out);
}

// round 9
// speedup vs baseline: 5.8597x; 1.1860x over previous
#include <cuda_runtime.h>
#include <cstdint>

// Single-head causal attention: B=32, T=1024, C=384, H=64 (fp32 in/out).
#define B_ 32
#define T_ 1024
#define C_ 384
#define H_ 64

// K/Q/V scratch: stored as canonical tf32 values (rounded at proj epilogue),
// so attention can cp.async them raw with no conversion.
__device__ float g_K[B_ * T_ * H_];
__device__ float g_Q[B_ * T_ * H_];
__device__ float g_V[B_ * T_ * H_];

// ---------------------------------------------------------------------------
// Helpers (legacy PTX only — valid on base sm_103 target).
// ---------------------------------------------------------------------------
__device__ __forceinline__ float to_tf32(float x) {
    float r;
    asm("cvt.rna.tf32.f32 %0, %1;" : "=f"(r) : "f"(x));
    return r;
}

__device__ __forceinline__ void mma_tf32_16x8x8(
    float& d0, float& d1, float& d2, float& d3,
    uint32_t a0, uint32_t a1, uint32_t a2, uint32_t a3,
    uint32_t b0, uint32_t b1)
{
    asm volatile(
        "mma.sync.aligned.m16n8k8.row.col.f32.tf32.tf32.f32 "
        "{%0,%1,%2,%3}, {%4,%5,%6,%7}, {%8,%9}, {%0,%1,%2,%3};"
        : "+f"(d0), "+f"(d1), "+f"(d2), "+f"(d3)
        : "r"(a0), "r"(a1), "r"(a2), "r"(a3), "r"(b0), "r"(b1));
}

__device__ __forceinline__ uint32_t smem_u32(const void* p) {
    uint32_t a;
    asm("{ .reg .u64 t; cvta.to.shared.u64 t, %1; cvt.u32.u64 %0, t; }"
        : "=r"(a) : "l"(p));
    return a;
}

__device__ __forceinline__ void cp_async16(float* dst, const float* src) {
    uint32_t d = smem_u32(dst);
    asm volatile("cp.async.cg.shared.global [%0], [%1], 16;"
                 :: "r"(d), "l"(src) : "memory");
}
#define CP_COMMIT() asm volatile("cp.async.commit_group;" ::: "memory")

// ===========================================================================
// Fused projection: one CTA computes K, Q, V for 64 rows of x.
// 128 thr = 4 warps, warp tile 16 rows x 64 cols x {K,Q,V}.
// x tile loaded once per chunk (A-frags amortized 3x). Outputs stored
// tf32-rounded (canonical) so attention skips conversion.
// ===========================================================================
#define PM 64
#define PKC 32
#define SA_STR 36
#define SB_STR 72

__global__ void __launch_bounds__(128, 3) proj_mma(
    const float* __restrict__ x,
    const float* __restrict__ Wk,
    const float* __restrict__ Wq,
    const float* __restrict__ Wv)
{
    __shared__ float sA[PM * SA_STR];          // 9.2 KB
    __shared__ float sB[3][PKC * SB_STR];      // 27.6 KB

    const int t = threadIdx.x;
    const int wid = t >> 5;
    const int lane = t & 31;
    const int g = lane >> 2;
    const int tig = lane & 3;
    const int wr0 = wid * 16;
    const int row0 = blockIdx.x * PM;

    const float* __restrict__ Ws[3] = { Wk, Wq, Wv };

    float acc[3][8][4];
#pragma unroll
    for (int w = 0; w < 3; w++)
#pragma unroll
        for (int nt = 0; nt < 8; nt++)
#pragma unroll
            for (int i = 0; i < 4; i++) acc[w][nt][i] = 0.0f;

    for (int c0 = 0; c0 < C_; c0 += PKC) {
        __syncthreads();
        // A tile: x[row0..+63][c0..+31], tf32-rounded. 512 float4 / 128 thr.
#pragma unroll
        for (int i = 0; i < 4; i++) {
            int f = t + i * 128;
            int row = f >> 3;
            int c4 = (f & 7) * 4;
            float4 v = *reinterpret_cast<const float4*>(
                x + (size_t)(row0 + row) * C_ + c0 + c4);
            float* d = &sA[row * SA_STR + c4];
            d[0] = to_tf32(v.x); d[1] = to_tf32(v.y);
            d[2] = to_tf32(v.z); d[3] = to_tf32(v.w);
        }
        // B tiles: W[c0+k][n] for all 3 weights. 1536 float4 / 128 thr.
#pragma unroll
        for (int i = 0; i < 12; i++) {
            int idx = t + i * 128;
            int w = idx >> 9;
            int rem = idx & 511;
            int k = rem >> 4;
            int n4 = (rem & 15) * 4;
            float4 v = *reinterpret_cast<const float4*>(
                Ws[w] + (size_t)(c0 + k) * H_ + n4);
            float* d = &sB[w][k * SB_STR + n4];
            d[0] = to_tf32(v.x); d[1] = to_tf32(v.y);
            d[2] = to_tf32(v.z); d[3] = to_tf32(v.w);
        }
        __syncthreads();

#pragma unroll
        for (int ks = 0; ks < 4; ks++) {
            const int k8 = ks * 8;
            uint32_t a0 = __float_as_uint(sA[(wr0 + g) * SA_STR + k8 + tig]);
            uint32_t a1 = __float_as_uint(sA[(wr0 + g + 8) * SA_STR + k8 + tig]);
            uint32_t a2 = __float_as_uint(sA[(wr0 + g) * SA_STR + k8 + tig + 4]);
            uint32_t a3 = __float_as_uint(sA[(wr0 + g + 8) * SA_STR + k8 + tig + 4]);
#pragma unroll
            for (int w = 0; w < 3; w++) {
#pragma unroll
                for (int nt = 0; nt < 8; nt++) {
                    uint32_t b0 = __float_as_uint(sB[w][(k8 + tig) * SB_STR + nt * 8 + g]);
                    uint32_t b1 = __float_as_uint(sB[w][(k8 + tig + 4) * SB_STR + nt * 8 + g]);
                    mma_tf32_16x8x8(acc[w][nt][0], acc[w][nt][1],
                                    acc[w][nt][2], acc[w][nt][3],
                                    a0, a1, a2, a3, b0, b1);
                }
            }
        }
    }

    // Epilogue: store tf32-rounded (canonical) values.
    float* __restrict__ outs[3] = { g_K, g_Q, g_V };
#pragma unroll
    for (int w = 0; w < 3; w++) {
#pragma unroll
        for (int nt = 0; nt < 8; nt++) {
            float* o0 = outs[w] + (size_t)(row0 + wr0 + g) * H_ + nt * 8 + 2 * tig;
            o0[0] = to_tf32(acc[w][nt][0]); o0[1] = to_tf32(acc[w][nt][1]);
            float* o1 = outs[w] + (size_t)(row0 + wr0 + g + 8) * H_ + nt * 8 + 2 * tig;
            o1[0] = to_tf32(acc[w][nt][2]); o1[1] = to_tf32(acc[w][nt][3]);
        }
    }
}

// ===========================================================================
// Tensor-core flash attention, double-buffered via cp.async.
// Block 128 thr = 4 warps; q-tile 64 (16 rows/warp), key-tile 64.
// Dynamic smem: Kbuf[2] stride 68, Vbuf[2] stride 72 (bank-conflict-free
// B-frag reads). K/V arrive as canonical tf32 (rounded at proj) — no cvt.
// Q fragments loaded directly from gmem (scaled + rounded in registers).
// ===========================================================================
#define KS_STR 68
#define VS_STR 72
#define KSZ (64 * KS_STR)
#define VSZ (64 * VS_STR)
#define ATTN_SMEM ((2 * KSZ + 2 * VSZ) * 4)

__global__ void __launch_bounds__(128, 2) attn_mma(float* __restrict__ out)
{
    extern __shared__ float dsm[];
    float* Kb0 = dsm;
    float* Kb1 = dsm + KSZ;
    float* Vb0 = dsm + 2 * KSZ;
    float* Vb1 = dsm + 2 * KSZ + VSZ;

    const int b = blockIdx.y;
    const int q0 = (15 - (int)blockIdx.x) * 64;   // heavy blocks first
    const int t = threadIdx.x;
    const int wid = t >> 5;
    const int lane = t & 31;
    const int g = lane >> 2;
    const int tig = lane & 3;
    const int m0 = wid * 16 + g;
    const float cs = 0.125f * 1.44269504f;        // H^-0.5 * log2(e)
    const int ntiles = q0 / 64 + 1;

    // --- Prefetch tile 0.
    {
        const float* Kg = g_K + ((size_t)(b << 10)) * H_;
        const float* Vg = g_V + ((size_t)(b << 10)) * H_;
#pragma unroll
        for (int i = 0; i < 8; i++) {
            int f4 = t + i * 128;
            int row = f4 >> 4, c4 = (f4 & 15) << 2;
            cp_async16(&Kb0[row * KS_STR + c4], Kg + row * H_ + c4);
            cp_async16(&Vb0[row * VS_STR + c4], Vg + row * H_ + c4);
        }
        CP_COMMIT();
    }

    // --- Q fragments: direct LDG, scale + round in registers.
    uint32_t q[8][4];
    {
        const float* Qg = g_Q + ((size_t)(b << 10) + q0) * H_;
#pragma unroll
        for (int kc = 0; kc < 8; kc++) {
            q[kc][0] = __float_as_uint(to_tf32(cs * Qg[m0 * H_ + kc * 8 + tig]));
            q[kc][1] = __float_as_uint(to_tf32(cs * Qg[(m0 + 8) * H_ + kc * 8 + tig]));
            q[kc][2] = __float_as_uint(to_tf32(cs * Qg[m0 * H_ + kc * 8 + tig + 4]));
            q[kc][3] = __float_as_uint(to_tf32(cs * Qg[(m0 + 8) * H_ + kc * 8 + tig + 4]));
        }
    }

    // --- Prefetch tile 1.
    if (ntiles > 1) {
        const float* Kg = g_K + ((size_t)(b << 10) + 64) * H_;
        const float* Vg = g_V + ((size_t)(b << 10) + 64) * H_;
#pragma unroll
        for (int i = 0; i < 8; i++) {
            int f4 = t + i * 128;
            int row = f4 >> 4, c4 = (f4 & 15) << 2;
            cp_async16(&Kb1[row * KS_STR + c4], Kg + row * H_ + c4);
            cp_async16(&Vb1[row * VS_STR + c4], Vg + row * H_ + c4);
        }
        CP_COMMIT();
    }

    float o[8][4];
#pragma unroll
    for (int nt = 0; nt < 8; nt++)
#pragma unroll
        for (int i = 0; i < 4; i++) o[nt][i] = 0.0f;
    float rmaxA = -1e30f, rmaxB = -1e30f, rsumA = 0.0f, rsumB = 0.0f;

    for (int ti = 0; ti < ntiles; ti++) {
        const int cur = ti & 1;
        float* Ks = cur ? Kb1 : Kb0;
        float* Vs = cur ? Vb1 : Vb0;

        // Wait for this tile's cp.async group (leave next tile's in flight).
        if (ti + 1 < ntiles) asm volatile("cp.async.wait_group 1;" ::: "memory");
        else                 asm volatile("cp.async.wait_group 0;" ::: "memory");
        __syncthreads();

        // --- S = Q''.K^T
        float s[8][4];
#pragma unroll
        for (int nt = 0; nt < 8; nt++)
#pragma unroll
            for (int i = 0; i < 4; i++) s[nt][i] = 0.0f;

#pragma unroll
        for (int kc = 0; kc < 8; kc++) {
#pragma unroll
            for (int nt = 0; nt < 8; nt++) {
                uint32_t b0 = __float_as_uint(Ks[(nt * 8 + g) * KS_STR + kc * 8 + tig]);
                uint32_t b1 = __float_as_uint(Ks[(nt * 8 + g) * KS_STR + kc * 8 + tig + 4]);
                mma_tf32_16x8x8(s[nt][0], s[nt][1], s[nt][2], s[nt][3],
                                q[kc][0], q[kc][1], q[kc][2], q[kc][3], b0, b1);
            }
        }

        // --- Causal mask (diagonal tile only).
        if (ti == ntiles - 1) {
#pragma unroll
            for (int nt = 0; nt < 8; nt++) {
                int c0 = nt * 8 + 2 * tig;
                if (c0 > m0)         s[nt][0] = -1e30f;
                if (c0 + 1 > m0)     s[nt][1] = -1e30f;
                if (c0 > m0 + 8)     s[nt][2] = -1e30f;
                if (c0 + 1 > m0 + 8) s[nt][3] = -1e30f;
            }
        }

        // --- Online softmax (rows spread over the 4 tig lanes).
        float tA = -1e30f, tB = -1e30f;
#pragma unroll
        for (int nt = 0; nt < 8; nt++) {
            tA = fmaxf(tA, fmaxf(s[nt][0], s[nt][1]));
            tB = fmaxf(tB, fmaxf(s[nt][2], s[nt][3]));
        }
        tA = fmaxf(tA, __shfl_xor_sync(0xffffffffu, tA, 1));
        tA = fmaxf(tA, __shfl_xor_sync(0xffffffffu, tA, 2));
        tB = fmaxf(tB, __shfl_xor_sync(0xffffffffu, tB, 1));
        tB = fmaxf(tB, __shfl_xor_sync(0xffffffffu, tB, 2));

        float nmA = fmaxf(rmaxA, tA), nmB = fmaxf(rmaxB, tB);
        float alA = exp2f(rmaxA - nmA), alB = exp2f(rmaxB - nmB);
        rmaxA = nmA; rmaxB = nmB;
        rsumA *= alA; rsumB *= alB;
#pragma unroll
        for (int nt = 0; nt < 8; nt++) {
            o[nt][0] *= alA; o[nt][1] *= alA;
            o[nt][2] *= alB; o[nt][3] *= alB;
        }

        float psA = 0.0f, psB = 0.0f;
#pragma unroll
        for (int nt = 0; nt < 8; nt++) {
            float p0 = to_tf32(exp2f(s[nt][0] - nmA));
            float p1 = to_tf32(exp2f(s[nt][1] - nmA));
            float p2 = to_tf32(exp2f(s[nt][2] - nmB));
            float p3 = to_tf32(exp2f(s[nt][3] - nmB));
            s[nt][0] = p0; s[nt][1] = p1; s[nt][2] = p2; s[nt][3] = p3;
            psA += p0 + p1; psB += p2 + p3;
        }
        psA += __shfl_xor_sync(0xffffffffu, psA, 1);
        psA += __shfl_xor_sync(0xffffffffu, psA, 2);
        psB += __shfl_xor_sync(0xffffffffu, psB, 1);
        psB += __shfl_xor_sync(0xffffffffu, psB, 2);
        rsumA += psA; rsumB += psB;

        // --- O += P.V  (P accum->A-frag via intra-quad shfl).
        const int srcA = (lane & ~3) | (tig >> 1);
        const int srcB = srcA + 2;
        const bool odd = (tig & 1) != 0;
#pragma unroll
        for (int kc = 0; kc < 8; kc++) {
            float e0 = __shfl_sync(0xffffffffu, s[kc][0], srcA);
            float e1 = __shfl_sync(0xffffffffu, s[kc][1], srcA);
            float e2 = __shfl_sync(0xffffffffu, s[kc][2], srcA);
            float e3 = __shfl_sync(0xffffffffu, s[kc][3], srcA);
            float f0 = __shfl_sync(0xffffffffu, s[kc][0], srcB);
            float f1 = __shfl_sync(0xffffffffu, s[kc][1], srcB);
            float f2 = __shfl_sync(0xffffffffu, s[kc][2], srcB);
            float f3 = __shfl_sync(0xffffffffu, s[kc][3], srcB);
            uint32_t a0 = __float_as_uint(odd ? e1 : e0);
            uint32_t a1 = __float_as_uint(odd ? e3 : e2);
            uint32_t a2 = __float_as_uint(odd ? f1 : f0);
            uint32_t a3 = __float_as_uint(odd ? f3 : f2);
#pragma unroll
            for (int nt = 0; nt < 8; nt++) {
                uint32_t b0 = __float_as_uint(Vs[(kc * 8 + tig) * VS_STR + nt * 8 + g]);
                uint32_t b1 = __float_as_uint(Vs[(kc * 8 + tig + 4) * VS_STR + nt * 8 + g]);
                mma_tf32_16x8x8(o[nt][0], o[nt][1], o[nt][2], o[nt][3],
                                a0, a1, a2, a3, b0, b1);
            }
        }

        __syncthreads();   // all warps done reading buffer cur

        // --- Prefetch tile ti+2 into buffer cur.
        if (ti + 2 < ntiles) {
            const float* Kg = g_K + ((size_t)(b << 10) + (ti + 2) * 64) * H_;
            const float* Vg = g_V + ((size_t)(b << 10) + (ti + 2) * 64) * H_;
#pragma unroll
            for (int i = 0; i < 8; i++) {
                int f4 = t + i * 128;
                int row = f4 >> 4, c4 = (f4 & 15) << 2;
                cp_async16(&Ks[row * KS_STR + c4], Kg + row * H_ + c4);
                cp_async16(&Vs[row * VS_STR + c4], Vg + row * H_ + c4);
            }
            CP_COMMIT();
        }
    }

    // --- Normalize + write.
    const float invA = 1.0f / rsumA, invB = 1.0f / rsumB;
    float* OrA = out + ((size_t)(b << 10) + q0 + m0) * H_;
    float* OrB = OrA + 8 * H_;
#pragma unroll
    for (int nt = 0; nt < 8; nt++) {
        *reinterpret_cast<float2*>(OrA + nt * 8 + 2 * tig) =
            make_float2(o[nt][0] * invA, o[nt][1] * invA);
        *reinterpret_cast<float2*>(OrB + nt * 8 + 2 * tig) =
            make_float2(o[nt][2] * invB, o[nt][3] * invB);
    }
}

// ===========================================================================
extern "C" void kernel_launch(void* const* d_in, const int* in_sizes, int n_in,
                              void* d_out, int out_size)
{
    const float* x  = (const float*)d_in[0];
    const float* Wk = (const float*)d_in[1];
    const float* Wq = (const float*)d_in[2];
    const float* Wv = (const float*)d_in[3];
    float* out = (float*)d_out;

    cudaFuncSetAttribute(attn_mma, cudaFuncAttributeMaxDynamicSharedMemorySize,
                         ATTN_SMEM);

    dim3 pg((B_ * T_) / PM);
    proj_mma<<<pg, 128>>>(x, Wk, Wq, Wv);

    dim3 ag(T_ / 64, B_);
    attn_mma<<<ag, 128, ATTN_SMEM>>>(out);
}